// round 1
// baseline (speedup 1.0000x reference)
#include <cuda_runtime.h>

// Problem constants (fixed by the dataset)
#define MAXN 50000
#define MAXE 800000

// Persistent device scratch (allocation-free rule: __device__ globals)
static __device__ __align__(16) float g_sup[MAXN * 32];     // s_up        [n][c]
static __device__ __align__(16) float g_vup[MAXN * 96];     // v_up        [n][x][c]
static __device__ __align__(16) float g_skip_s[MAXN * 64];  // skip_s      [n][d]
static __device__ __align__(16) float g_skip_v[MAXN * 96];  // skip_v      [n][x][c]
static __device__ __align__(16) float g_agg[MAXN * 256];    // [n][slot][c]: slot0=agg0(64), slot1..3=agg1 x(64)

__device__ __forceinline__ float silu_f(float x) {
    return x / (1.0f + __expf(-x));
}

__device__ __forceinline__ void red_add_v4(float* p, float a, float b, float c, float d) {
    asm volatile("red.global.add.v4.f32 [%0], {%1,%2,%3,%4};"
                 :: "l"(p), "f"(a), "f"(b), "f"(c), "f"(d)
                 : "memory");
}

// ---------------------------------------------------------------------------
// Kernel A: per-node up-projection + species-dependent skip + agg zeroing.
// Warp per node; lane = channel.
// ---------------------------------------------------------------------------
__global__ void node_up_kernel(const float* __restrict__ nf,
                               const int*   __restrict__ species,
                               const float* __restrict__ Wus,   // (32,32)
                               const float* __restrict__ Wuv,   // (32,32)
                               const float* __restrict__ Wss,   // (5,32,64)
                               const float* __restrict__ Wsv,   // (5,32,32)
                               int N)
{
    int warp = (blockIdx.x * blockDim.x + threadIdx.x) >> 5;
    int lane = threadIdx.x & 31;
    if (warp >= N) return;
    int n = warp;

    const float* nfp = nf + (size_t)n * 128;
    float s  = nfp[lane];
    float v0 = nfp[32 + lane * 3 + 0];
    float v1 = nfp[32 + lane * 3 + 1];
    float v2 = nfp[32 + lane * 3 + 2];
    int sp = species[n];
    const float* wss = Wss + sp * 2048;
    const float* wsv = Wsv + sp * 1024;

    float sup = 0.f, vu0 = 0.f, vu1 = 0.f, vu2 = 0.f;
    float ss0 = 0.f, ss1 = 0.f, sv0 = 0.f, sv1 = 0.f, sv2 = 0.f;

    #pragma unroll
    for (int c = 0; c < 32; ++c) {
        float sb = __shfl_sync(0xffffffffu, s,  c);
        float b0 = __shfl_sync(0xffffffffu, v0, c);
        float b1 = __shfl_sync(0xffffffffu, v1, c);
        float b2 = __shfl_sync(0xffffffffu, v2, c);
        sup = fmaf(sb, __ldg(Wus + c * 32 + lane), sup);
        float wu = __ldg(Wuv + c * 32 + lane);
        vu0 = fmaf(b0, wu, vu0);
        vu1 = fmaf(b1, wu, vu1);
        vu2 = fmaf(b2, wu, vu2);
        ss0 = fmaf(sb, __ldg(wss + c * 64 + lane), ss0);
        ss1 = fmaf(sb, __ldg(wss + c * 64 + 32 + lane), ss1);
        float wv = __ldg(wsv + c * 32 + lane);
        sv0 = fmaf(b0, wv, sv0);
        sv1 = fmaf(b1, wv, sv1);
        sv2 = fmaf(b2, wv, sv2);
    }

    const float isc = 0.17677669529663687f; // 1/sqrt(32)
    g_sup[n * 32 + lane]           = sup * isc;
    g_vup[n * 96 + 0 * 32 + lane]  = vu0 * isc;
    g_vup[n * 96 + 1 * 32 + lane]  = vu1 * isc;
    g_vup[n * 96 + 2 * 32 + lane]  = vu2 * isc;
    g_skip_s[n * 64 + lane]        = ss0 * isc;
    g_skip_s[n * 64 + 32 + lane]   = ss1 * isc;
    g_skip_v[n * 96 + 0 * 32 + lane] = sv0 * isc;
    g_skip_v[n * 96 + 1 * 32 + lane] = sv1 * isc;
    g_skip_v[n * 96 + 2 * 32 + lane] = sv2 * isc;

    // Zero this node's accumulator slab (must precede edge kernel).
    #pragma unroll
    for (int k = 0; k < 8; ++k)
        g_agg[n * 256 + k * 32 + lane] = 0.f;
}

// ---------------------------------------------------------------------------
// Kernel B: edge kernel. Warp per edge.
// Lane layout: producer lane P computes w[path=P>>3][4*(P&7)..+3].
// Consumer lane L owns two float4 scatter targets:
//   qA = L     -> slot L>>4        (0: agg0, 1: agg1 x=0), chans 4*(L&15)..
//   qB = L+32  -> slot (L>>4)+2    (2: agg1 x=1, 3: agg1 x=2)
// ---------------------------------------------------------------------------
__global__ void edge_kernel(const float* __restrict__ ef,
                            const float* __restrict__ radial,
                            const int*   __restrict__ snd_,
                            const int*   __restrict__ rcv_,
                            const float* __restrict__ Wr1,   // (8,8)
                            const float* __restrict__ Wr2,   // (8,128)
                            int E)
{
    int warp = (blockIdx.x * blockDim.x + threadIdx.x) >> 5;
    int lane = threadIdx.x & 31;
    if (warp >= E) return;
    int e = warp;

    int snd = __ldg(snd_ + e);
    int rcv = __ldg(rcv_ + e);

    const float inv_sqrt8 = 0.35355339059327373f;
    const float inv_sqrt3 = 0.5773502691896258f;
    const float qdeg      = 0.25f; // 1/sqrt(16)

    // radial MLP hidden layer: every lane computes h[lane&7] (lanes 8..31 redundant)
    float h = 0.f;
    {
        const float* r = radial + (size_t)e * 8;
        int j = lane & 7;
        #pragma unroll
        for (int i = 0; i < 8; ++i)
            h = fmaf(__ldg(r + i), __ldg(Wr1 + i * 8 + j), h);
        h = silu_f(h * inv_sqrt8);
    }
    float hj[8];
    #pragma unroll
    for (int j = 0; j < 8; ++j) hj[j] = __shfl_sync(0xffffffffu, h, j);

    // producer w: path p = lane>>3, channels 4*(lane&7)..+3  ==  Wr2 col 4*lane..
    float w0 = 0.f, w1 = 0.f, w2 = 0.f, w3 = 0.f;
    #pragma unroll
    for (int j = 0; j < 8; ++j) {
        float4 wr = __ldg((const float4*)(Wr2 + j * 128 + lane * 4));
        w0 = fmaf(hj[j], wr.x, w0);
        w1 = fmaf(hj[j], wr.y, w1);
        w2 = fmaf(hj[j], wr.z, w2);
        w3 = fmaf(hj[j], wr.w, w3);
    }
    w0 *= inv_sqrt8; w1 *= inv_sqrt8; w2 *= inv_sqrt8; w3 *= inv_sqrt8;

    // redistribute w to consumers
    int grp  = lane >> 3;
    int srcA = (grp == 0) ? lane : ((grp == 1) ? lane + 16 : lane - 8);
    int srcB = (grp < 2)  ? lane + 8 : srcA;
    float wA0 = __shfl_sync(0xffffffffu, w0, srcA);
    float wA1 = __shfl_sync(0xffffffffu, w1, srcA);
    float wA2 = __shfl_sync(0xffffffffu, w2, srcA);
    float wA3 = __shfl_sync(0xffffffffu, w3, srcA);
    float wB0 = __shfl_sync(0xffffffffu, w0, srcB);
    float wB1 = __shfl_sync(0xffffffffu, w1, srcB);
    float wB2 = __shfl_sync(0xffffffffu, w2, srcB);
    float wB3 = __shfl_sync(0xffffffffu, w3, srcB);

    // spherical parts: sh0 = ef[0], sh1 = ef[1:4]
    float4 sh = __ldg((const float4*)(ef + (size_t)e * 4));

    int cidx = (lane & 7) * 4;
    float vA0, vA1, vA2, vA3, vB0, vB1, vB2, vB3;

    if ((grp & 1) == 0) {
        // scalar channels: need s_up[snd]
        float4 se = __ldg((const float4*)(g_sup + (size_t)snd * 32 + cidx));
        if (grp == 0) {
            // qA: agg0 first half = w0*se*sh0 ; qB: agg1 x=1 first half = w1*se*sh1[1]
            vA0 = wA0 * se.x * sh.x; vA1 = wA1 * se.y * sh.x;
            vA2 = wA2 * se.z * sh.x; vA3 = wA3 * se.w * sh.x;
            vB0 = wB0 * se.x * sh.z; vB1 = wB1 * se.y * sh.z;
            vB2 = wB2 * se.z * sh.z; vB3 = wB3 * se.w * sh.z;
        } else {
            // grp2 (wA = w1): qA: agg1 x=0 = w1*se*sh1[0]; qB: agg1 x=2 = w1*se*sh1[2]
            vA0 = wA0 * se.x * sh.y; vA1 = wA1 * se.y * sh.y;
            vA2 = wA2 * se.z * sh.y; vA3 = wA3 * se.w * sh.y;
            vB0 = wA0 * se.x * sh.w; vB1 = wA1 * se.y * sh.w;
            vB2 = wA2 * se.z * sh.w; vB3 = wA3 * se.w * sh.w;
        }
    } else {
        // vector channels: need v_up[snd]
        const float* vb = g_vup + (size_t)snd * 96 + cidx;
        if (grp == 1) {
            float4 ve0 = __ldg((const float4*)(vb));
            float4 ve1 = __ldg((const float4*)(vb + 32));
            float4 ve2 = __ldg((const float4*)(vb + 64));
            // qA: agg0 second half = w3 * dot(ve, sh1) / sqrt(3)   (wA = w3)
            float d0 = ve0.x * sh.y + ve1.x * sh.z + ve2.x * sh.w;
            float d1 = ve0.y * sh.y + ve1.y * sh.z + ve2.y * sh.w;
            float d2 = ve0.z * sh.y + ve1.z * sh.z + ve2.z * sh.w;
            float d3 = ve0.w * sh.y + ve1.w * sh.z + ve2.w * sh.w;
            vA0 = wA0 * d0 * inv_sqrt3; vA1 = wA1 * d1 * inv_sqrt3;
            vA2 = wA2 * d2 * inv_sqrt3; vA3 = wA3 * d3 * inv_sqrt3;
            // qB: agg1 x=1 second half = w2 * ve[:,1] * sh0       (wB = w2)
            vB0 = wB0 * ve1.x * sh.x; vB1 = wB1 * ve1.y * sh.x;
            vB2 = wB2 * ve1.z * sh.x; vB3 = wB3 * ve1.w * sh.x;
        } else {
            // grp3 (wA = w2): qA: agg1 x=0 second half = w2*ve[:,0]*sh0
            //                 qB: agg1 x=2 second half = w2*ve[:,2]*sh0
            float4 ve0 = __ldg((const float4*)(vb));
            float4 ve2 = __ldg((const float4*)(vb + 64));
            vA0 = wA0 * ve0.x * sh.x; vA1 = wA1 * ve0.y * sh.x;
            vA2 = wA2 * ve0.z * sh.x; vA3 = wA3 * ve0.w * sh.x;
            vB0 = wA0 * ve2.x * sh.x; vB1 = wA1 * ve2.y * sh.x;
            vB2 = wA2 * ve2.z * sh.x; vB3 = wA3 * ve2.w * sh.x;
        }
    }

    float* dst = g_agg + (size_t)rcv * 256 + (lane >> 4) * 64 + (lane & 15) * 4;
    red_add_v4(dst,       vA0 * qdeg, vA1 * qdeg, vA2 * qdeg, vA3 * qdeg);
    red_add_v4(dst + 128, vB0 * qdeg, vB1 * qdeg, vB2 * qdeg, vB3 * qdeg);
}

// ---------------------------------------------------------------------------
// Kernel C: per-node down-projection + skip average + gated output.
// Warp per node; lane = output channel.
// ---------------------------------------------------------------------------
__global__ void node_down_kernel(const float* __restrict__ Wds,  // (64,64)
                                 const float* __restrict__ Wdv,  // (64,32)
                                 float* __restrict__ out,
                                 int N)
{
    int warp = (blockIdx.x * blockDim.x + threadIdx.x) >> 5;
    int lane = threadIdx.x & 31;
    if (warp >= N) return;
    int n = warp;

    const float* ag = g_agg + (size_t)n * 256;
    float a0l  = ag[lane],        a0h  = ag[32 + lane];
    float a1l0 = ag[64 + lane],   a1h0 = ag[96 + lane];
    float a1l1 = ag[128 + lane],  a1h1 = ag[160 + lane];
    float a1l2 = ag[192 + lane],  a1h2 = ag[224 + lane];

    float sc0 = 0.f, sc1 = 0.f, vc0 = 0.f, vc1 = 0.f, vc2 = 0.f;

    #pragma unroll
    for (int c = 0; c < 32; ++c) {
        float b0 = __shfl_sync(0xffffffffu, a0l, c);
        float b1 = __shfl_sync(0xffffffffu, a0h, c);
        sc0 = fmaf(b0, __ldg(Wds + c * 64 + lane), sc0);
        sc0 = fmaf(b1, __ldg(Wds + (32 + c) * 64 + lane), sc0);
        sc1 = fmaf(b0, __ldg(Wds + c * 64 + 32 + lane), sc1);
        sc1 = fmaf(b1, __ldg(Wds + (32 + c) * 64 + 32 + lane), sc1);
        float wv0 = __ldg(Wdv + c * 32 + lane);
        float wv1 = __ldg(Wdv + (32 + c) * 32 + lane);
        vc0 = fmaf(__shfl_sync(0xffffffffu, a1l0, c), wv0, vc0);
        vc0 = fmaf(__shfl_sync(0xffffffffu, a1h0, c), wv1, vc0);
        vc1 = fmaf(__shfl_sync(0xffffffffu, a1l1, c), wv0, vc1);
        vc1 = fmaf(__shfl_sync(0xffffffffu, a1h1, c), wv1, vc1);
        vc2 = fmaf(__shfl_sync(0xffffffffu, a1l2, c), wv0, vc2);
        vc2 = fmaf(__shfl_sync(0xffffffffu, a1h2, c), wv1, vc2);
    }

    const float i2c = 0.125f; // 1/sqrt(64)
    float scl = 0.5f * (sc0 * i2c + g_skip_s[n * 64 + lane]);
    float sch = 0.5f * (sc1 * i2c + g_skip_s[n * 64 + 32 + lane]);
    float feat = silu_f(scl);
    float gate = silu_f(sch);

    float vg0 = 0.5f * (vc0 * i2c + g_skip_v[n * 96 +      lane]) * gate;
    float vg1 = 0.5f * (vc1 * i2c + g_skip_v[n * 96 + 32 + lane]) * gate;
    float vg2 = 0.5f * (vc2 * i2c + g_skip_v[n * 96 + 64 + lane]) * gate;

    float* o = out + (size_t)n * 128;
    o[lane] = feat;
    o[32 + 3 * lane + 0] = vg0;
    o[32 + 3 * lane + 1] = vg1;
    o[32 + 3 * lane + 2] = vg2;
}

// ---------------------------------------------------------------------------
extern "C" void kernel_launch(void* const* d_in, const int* in_sizes, int n_in,
                              void* d_out, int out_size)
{
    const float* nf      = (const float*)d_in[0];
    const float* ef      = (const float*)d_in[1];
    const float* radial  = (const float*)d_in[2];
    const int*   snd     = (const int*)  d_in[3];
    const int*   rcv     = (const int*)  d_in[4];
    const int*   species = (const int*)  d_in[5];
    const float* Wus     = (const float*)d_in[6];
    const float* Wuv     = (const float*)d_in[7];
    const float* Wr1     = (const float*)d_in[8];
    const float* Wr2     = (const float*)d_in[9];
    const float* Wds     = (const float*)d_in[10];
    const float* Wdv     = (const float*)d_in[11];
    const float* Wss     = (const float*)d_in[12];
    const float* Wsv     = (const float*)d_in[13];
    float* out = (float*)d_out;

    int N = in_sizes[0] / 128;
    int E = in_sizes[3];

    node_up_kernel  <<<(N + 7) / 8, 256>>>(nf, species, Wus, Wuv, Wss, Wsv, N);
    edge_kernel     <<<(E + 7) / 8, 256>>>(ef, radial, snd, rcv, Wr1, Wr2, E);
    node_down_kernel<<<(N + 7) / 8, 256>>>(Wds, Wdv, out, N);
}